// round 15
// baseline (speedup 1.0000x reference)
#include <cuda_runtime.h>
#include <cuda_bf16.h>
#include <math.h>
#include <stdint.h>

#define VOCAB 32000
#define DIM   300
#define KPAD  304     // 19 * 16, zero-padded K
#define B_    128
#define T_    512
#define H_    128
#define G3    384     // 3*H

// Scratch (static device memory, allocation-free):
__device__ float g_proj[2][VOCAB * G3];                 // 98.3 MB
__device__ __nv_bfloat16 g_embH[VOCAB * KPAD];          // 19.5 MB
__device__ __nv_bfloat16 g_embL[VOCAB * KPAD];          // 19.5 MB
__device__ __nv_bfloat16 g_WH[2][G3 * KPAD];            // [dir][n][k] transposed
__device__ __nv_bfloat16 g_WL[2][G3 * KPAD];

// ---- packed f32x2 helpers ---------------------------------------------------
__device__ __forceinline__ unsigned long long ffma2(
    unsigned long long a, unsigned long long b, unsigned long long c) {
    unsigned long long d;
    asm("fma.rn.f32x2 %0, %1, %2, %3;" : "=l"(d) : "l"(a), "l"(b), "l"(c));
    return d;
}
__device__ __forceinline__ unsigned long long pack2(float lo, float hi) {
    unsigned long long r;
    asm("mov.b64 %0, {%1, %2};" : "=l"(r) : "f"(lo), "f"(hi));
    return r;
}
__device__ __forceinline__ float2 unpack2(unsigned long long v) {
    float lo, hi;
    asm("mov.b64 {%0, %1}, %2;" : "=f"(lo), "=f"(hi) : "l"(v));
    return make_float2(lo, hi);
}
__device__ __forceinline__ unsigned long long d_as_ull(double d) {
    return __double_as_longlong(d);
}
__device__ __forceinline__ float fsigmoid(float x) {
    const float e = __expf(-x);
    return __fdividef(1.f, 1.f + e);
}
__device__ __forceinline__ float ftanh(float y) {
    const float e = __expf(-2.f * y);
    const float s = __fdividef(1.f, 1.f + e);
    return fmaf(2.f, s, -1.f);
}

// ---- warp-MMA helpers (baseline PTX, sm_80+) -------------------------------
__device__ __forceinline__ uint32_t smem_u32(const void* p) {
    uint32_t a;
    asm("{ .reg .u64 t; cvta.to.shared.u64 t, %1; cvt.u32.u64 %0, t; }"
        : "=r"(a) : "l"(p));
    return a;
}
__device__ __forceinline__ void ldm_x4(uint32_t& r0, uint32_t& r1,
                                       uint32_t& r2, uint32_t& r3,
                                       uint32_t addr) {
    asm volatile("ldmatrix.sync.aligned.m8n8.x4.shared.b16 {%0,%1,%2,%3}, [%4];"
                 : "=r"(r0), "=r"(r1), "=r"(r2), "=r"(r3) : "r"(addr));
}
__device__ __forceinline__ void mma_bf16(float* c, const uint32_t* a,
                                         const uint32_t* b) {
    asm volatile(
        "mma.sync.aligned.m16n8k16.row.col.f32.bf16.bf16.f32 "
        "{%0,%1,%2,%3}, {%4,%5,%6,%7}, {%8,%9}, {%0,%1,%2,%3};"
        : "+f"(c[0]), "+f"(c[1]), "+f"(c[2]), "+f"(c[3])
        : "r"(a[0]), "r"(a[1]), "r"(a[2]), "r"(a[3]), "r"(b[0]), "r"(b[1]));
}
__device__ __forceinline__ void cp_async16(uint32_t smem_addr,
                                           const void* gptr) {
    asm volatile("cp.async.cg.shared.global [%0], [%1], 16;"
                 :: "r"(smem_addr), "l"(gptr));
}
#define CP_COMMIT() asm volatile("cp.async.commit_group;" ::: "memory")
#define CP_WAIT1()  asm volatile("cp.async.wait_group 1;" ::: "memory")

__device__ __forceinline__ void cvt8_hilo(const float* v, uint4& H, uint4& L) {
    uint32_t hw[4], lw[4];
    #pragma unroll
    for (int q = 0; q < 4; q++) {
        const __nv_bfloat16 h0 = __float2bfloat16(v[2 * q]);
        const __nv_bfloat16 h1 = __float2bfloat16(v[2 * q + 1]);
        const __nv_bfloat16 l0 = __float2bfloat16(v[2 * q] - __bfloat162float(h0));
        const __nv_bfloat16 l1 = __float2bfloat16(v[2 * q + 1] - __bfloat162float(h1));
        hw[q] = (uint32_t)__bfloat16_as_ushort(h0) |
                ((uint32_t)__bfloat16_as_ushort(h1) << 16);
        lw[q] = (uint32_t)__bfloat16_as_ushort(l0) |
                ((uint32_t)__bfloat16_as_ushort(l1) << 16);
    }
    H = make_uint4(hw[0], hw[1], hw[2], hw[3]);
    L = make_uint4(lw[0], lw[1], lw[2], lw[3]);
}

// ---------------------------------------------------------------------------
// Fused prep kernel: one-time fp32 -> bf16 hi/lo conversion.
// ---------------------------------------------------------------------------
#define EITEMS (VOCAB * (KPAD / 8))
#define WITEMS (2 * G3 * (KPAD / 8))
#define EBLK   ((EITEMS + 255) / 256)
#define WBLK   ((WITEMS + 255) / 256)

__global__ __launch_bounds__(256)
void prep_kernel(const float* __restrict__ emb,
                 const float* __restrict__ W_f,
                 const float* __restrict__ W_b) {
    if (blockIdx.x < EBLK) {
        const int idx = blockIdx.x * 256 + threadIdx.x;
        if (idx >= EITEMS) return;
        const int v = idx / (KPAD / 8);
        const int k0 = (idx % (KPAD / 8)) * 8;
        float val[8];
        const float* src = emb + (size_t)v * DIM + k0;
        if (k0 + 7 < DIM) {
            const float4 f0 = *reinterpret_cast<const float4*>(src);
            const float4 f1 = *reinterpret_cast<const float4*>(src + 4);
            val[0] = f0.x; val[1] = f0.y; val[2] = f0.z; val[3] = f0.w;
            val[4] = f1.x; val[5] = f1.y; val[6] = f1.z; val[7] = f1.w;
        } else {
            #pragma unroll
            for (int j = 0; j < 8; j++)
                val[j] = (k0 + j < DIM) ? src[j] : 0.f;
        }
        uint4 H, L;
        cvt8_hilo(val, H, L);
        *reinterpret_cast<uint4*>(&g_embH[(size_t)v * KPAD + k0]) = H;
        *reinterpret_cast<uint4*>(&g_embL[(size_t)v * KPAD + k0]) = L;
    } else {
        const int idx = (blockIdx.x - EBLK) * 256 + threadIdx.x;
        if (idx >= WITEMS) return;
        const int dir = idx / (G3 * (KPAD / 8));
        const int rem = idx % (G3 * (KPAD / 8));
        const int n   = rem / (KPAD / 8);
        const int k0  = (rem % (KPAD / 8)) * 8;
        const float* W = dir ? W_b : W_f;
        float val[8];
        #pragma unroll
        for (int j = 0; j < 8; j++) {
            const int k = k0 + j;
            val[j] = (k < DIM) ? W[(size_t)k * G3 + n] : 0.f;
        }
        uint4 H, L;
        cvt8_hilo(val, H, L);
        *reinterpret_cast<uint4*>(&g_WH[dir][(size_t)n * KPAD + k0]) = H;
        *reinterpret_cast<uint4*>(&g_WL[dir][(size_t)n * KPAD + k0]) = L;
    }
}

// ---------------------------------------------------------------------------
// Tensor-core projection: 3-stage cp.async pipeline, ONE barrier per chunk,
// 48-byte tile row pitch (conflict-free ldmatrix).
// Pipeline invariant at iter ch: stage ch arrived, ch+1 in flight; after the
// barrier all warps have finished reading stage ch-1, so its buffer
// ((ch+2)%3) is immediately refilled with stage ch+2 -> ~2 chunks (~1000+cyc)
// of DRAM-latency cover.
// CTA: 128M x 128N, 8 warps, warp tile 64x32, mma m16n8k16,
// 3-term bf16 split, fp32 accumulators. Dynamic SMEM 73.7 KB, 2 CTAs/SM.
// ---------------------------------------------------------------------------
#define NCH 19
#define STG 3
#define ROWB 48
#define TILEB (128 * ROWB)              // 6144 B
#define STAGEB (4 * TILEB)              // 24576 B
#define SMEMB (STG * STAGEB)            // 73728 B

__global__ __launch_bounds__(256, 2)
void proj_mma_kernel(const float* __restrict__ b_f,
                     const float* __restrict__ b_b) {
    extern __shared__ char smem[];

    const int dir = blockIdx.z;
    const float* bi = dir ? b_b : b_f;   // row 0 = b_i
    const int vBase = blockIdx.x * 128;
    const int nBase = blockIdx.y * 128;

    const int tid  = threadIdx.x;
    const int lane = tid & 31;
    const int wid  = tid >> 5;
    const int wm   = (wid >> 2) * 64;
    const int wn   = (wid & 3) * 32;

    const int sr = tid >> 1;             // 0..127
    const int sk = (tid & 1) * 8;        // element offset 0 / 8

    const __nv_bfloat16* embH = g_embH + (size_t)(vBase + sr) * KPAD + sk;
    const __nv_bfloat16* embL = g_embL + (size_t)(vBase + sr) * KPAD + sk;
    const __nv_bfloat16* WHp  = &g_WH[dir][(size_t)(nBase + sr) * KPAD + sk];
    const __nv_bfloat16* WLp  = &g_WL[dir][(size_t)(nBase + sr) * KPAD + sk];

    const uint32_t smem0 = smem_u32(smem);
    const uint32_t dst   = smem0 + (uint32_t)(sr * ROWB + sk * 2);

    auto issue_stage = [&](int ch, int buf) {
        const int kc = ch * 16;
        const uint32_t o = (uint32_t)(buf * STAGEB);
        cp_async16(dst + o + 0 * TILEB, embH + kc);
        cp_async16(dst + o + 1 * TILEB, embL + kc);
        cp_async16(dst + o + 2 * TILEB, WHp + kc);
        cp_async16(dst + o + 3 * TILEB, WLp + kc);
    };

    const int grp = lane >> 3;
    const int rin = lane & 7;
    const int a_row_off = (grp & 1) * 8 + rin;
    const int a_col_off = (grp >> 1) * 8;
    const int b_row_off = (grp >> 1) * 8 + rin;
    const int b_col_off = (grp & 1) * 8;

    float acc[4][4][4];
    #pragma unroll
    for (int i = 0; i < 4; i++)
        #pragma unroll
        for (int j = 0; j < 4; j++)
            #pragma unroll
            for (int q = 0; q < 4; q++) acc[i][j][q] = 0.f;

    // prologue: stages 0,1 in flight
    issue_stage(0, 0); CP_COMMIT();
    issue_stage(1, 1); CP_COMMIT();

    for (int ch = 0; ch < NCH; ch++) {
        const int buf = ch % STG;
        CP_WAIT1();            // stage ch arrived (ch+1 still in flight)
        __syncthreads();       // data visible; all reads of stage ch-1 done

        // refill (ch-1)'s buffer with stage ch+2 — maximal lookahead
        if (ch + 2 < NCH) issue_stage(ch + 2, (ch + 2) % STG);
        CP_COMMIT();           // uniform group accounting

        const uint32_t base = smem0 + (uint32_t)(buf * STAGEB);
        const uint32_t ah = base + 0 * TILEB;
        const uint32_t al = base + 1 * TILEB;
        const uint32_t bh = base + 2 * TILEB;
        const uint32_t bl = base + 3 * TILEB;

        uint32_t Bhf[2][4], Blf[2][4];
        #pragma unroll
        for (int ip = 0; ip < 2; ip++) {
            const uint32_t boff =
                (uint32_t)((wn + ip * 16 + b_row_off) * ROWB + b_col_off * 2);
            ldm_x4(Bhf[ip][0], Bhf[ip][1], Bhf[ip][2], Bhf[ip][3], bh + boff);
            ldm_x4(Blf[ip][0], Blf[ip][1], Blf[ip][2], Blf[ip][3], bl + boff);
        }
        uint32_t Af[4][4];
        #pragma unroll
        for (int im = 0; im < 4; im++) {
            const uint32_t aoff =
                (uint32_t)((wm + im * 16 + a_row_off) * ROWB + a_col_off * 2);
            ldm_x4(Af[im][0], Af[im][1], Af[im][2], Af[im][3], ah + aoff);
        }
        // term 0: Ahi*Bhi ; term 1: Ahi*Blo
        #pragma unroll
        for (int im = 0; im < 4; im++)
            #pragma unroll
            for (int ip = 0; ip < 2; ip++) {
                mma_bf16(acc[im][ip * 2 + 0], Af[im], &Bhf[ip][0]);
                mma_bf16(acc[im][ip * 2 + 1], Af[im], &Bhf[ip][2]);
                mma_bf16(acc[im][ip * 2 + 0], Af[im], &Blf[ip][0]);
                mma_bf16(acc[im][ip * 2 + 1], Af[im], &Blf[ip][2]);
            }
        // term 2: Alo*Bhi
        #pragma unroll
        for (int im = 0; im < 4; im++) {
            const uint32_t aoff =
                (uint32_t)((wm + im * 16 + a_row_off) * ROWB + a_col_off * 2);
            ldm_x4(Af[im][0], Af[im][1], Af[im][2], Af[im][3], al + aoff);
        }
        #pragma unroll
        for (int im = 0; im < 4; im++)
            #pragma unroll
            for (int ip = 0; ip < 2; ip++) {
                mma_bf16(acc[im][ip * 2 + 0], Af[im], &Bhf[ip][0]);
                mma_bf16(acc[im][ip * 2 + 1], Af[im], &Bhf[ip][2]);
            }
        // no trailing barrier: next iteration's post-wait barrier protects
        // the buffer refill ordering.
    }

    // ---- epilogue: add bias, store fp32 ----
    float* outp = g_proj[dir];
    #pragma unroll
    for (int im = 0; im < 4; im++) {
        const int m = vBase + wm + im * 16 + (lane >> 2);
        #pragma unroll
        for (int in = 0; in < 4; in++) {
            const int n = nBase + wn + in * 8 + (lane & 3) * 2;
            const float b0 = __ldg(&bi[n]);
            const float b1 = __ldg(&bi[n + 1]);
            float* o0 = outp + (size_t)m * G3 + n;
            float* o1 = o0 + 8 * G3;
            *reinterpret_cast<float2*>(o0) =
                make_float2(acc[im][in][0] + b0, acc[im][in][1] + b1);
            *reinterpret_cast<float2*>(o1) =
                make_float2(acc[im][in][2] + b0, acc[im][in][3] + b1);
        }
    }
}

// ---------------------------------------------------------------------------
// GRU scan kernel (frozen: exact R11 version, measured 542-545 us).
// ---------------------------------------------------------------------------
__global__ __launch_bounds__(384, 1)
void scan_kernel(const int*   __restrict__ enc,
                 const float* __restrict__ state_fwd,
                 const float* __restrict__ state_back,
                 const float* __restrict__ U_f,
                 const float* __restrict__ b_f,
                 const float* __restrict__ U_b,
                 const float* __restrict__ b_b,
                 float*       __restrict__ out) {
    const int dir = blockIdx.y;
    const int b0  = blockIdx.x * 2;
    const int g   = threadIdx.x;          // 0..383

    const float* U     = dir ? U_b : U_f;
    const float* br    = (dir ? b_b : b_f) + G3;   // row 1 = b_r
    const float* state = dir ? state_back : state_fwd;
    const float* proj  = g_proj[dir];

    __shared__ __align__(16) float h_sh[2 * H_];
    __shared__ float rec_sh[2 * G3];
    __shared__ float xp_sh[2][2 * G3];
    __shared__ int   tok_sh[2][T_];

    unsigned long long Up[64];
    #pragma unroll
    for (int i = 0; i < 64; i++)
        Up[i] = pack2(U[(size_t)(2 * i) * G3 + g],
                      U[(size_t)(2 * i + 1) * G3 + g]);
    const float brg = br[g];

    for (int i = g; i < 2 * T_; i += 384) {
        const int b = i >> 9, t = i & (T_ - 1);
        tok_sh[b][t] = enc[(size_t)(b0 + b) * T_ + t];
    }

    const int gb = g >> 7, gj = g & 127;          // valid for g < 256
    float* out_ptr = out + (size_t)((b0 + gb) * T_ + (dir ? T_ - 1 : 0)) * (2 * H_)
                   + dir * H_ + gj;
    const long out_stride = (dir ? -1 : 1) * (long)(2 * H_);

    if (g < 256)
        h_sh[gb * H_ + gj] = state[(size_t)(b0 + gb) * H_ + gj];

    float bufA[2], bufB[2];
    {
        const int t0 = dir ? (T_ - 1) : 0;
        const int t1 = dir ? (T_ - 2) : 1;
        xp_sh[0][0 * G3 + g] = proj[(size_t)enc[(size_t)b0 * T_ + t0] * G3 + g];
        xp_sh[0][1 * G3 + g] = proj[(size_t)enc[(size_t)(b0 + 1) * T_ + t0] * G3 + g];
        bufA[1] = __ldg(&proj[(size_t)enc[(size_t)b0 * T_ + t1] * G3 + g]);
        bufB[1] = __ldg(&proj[(size_t)enc[(size_t)(b0 + 1) * T_ + t1] * G3 + g]);
        bufA[0] = 0.f; bufB[0] = 0.f;
    }
    __syncthreads();

    int cur = 0;
    #pragma unroll 2
    for (int s = 0; s < T_; s++) {
        const int s2 = (s + 2 < T_) ? (s + 2) : (T_ - 1);
        const int t2 = dir ? (T_ - 1 - s2) : s2;
        const float fa = __ldg(&proj[(size_t)tok_sh[0][t2] * G3 + g]);
        const float fb = __ldg(&proj[(size_t)tok_sh[1][t2] * G3 + g]);

        xp_sh[cur ^ 1][0 * G3 + g] = bufA[(s + 1) & 1];
        xp_sh[cur ^ 1][1 * G3 + g] = bufB[(s + 1) & 1];

        unsigned long long a0 = 0ull, a1 = 0ull;
        unsigned long long a2 = 0ull, a3 = 0ull;
        const double2* h0p = reinterpret_cast<const double2*>(h_sh);
        const double2* h1p = reinterpret_cast<const double2*>(h_sh + H_);
        #pragma unroll
        for (int j = 0; j < 32; j++) {
            const double2 da = h0p[j];
            const double2 db = h1p[j];
            a0 = ffma2(d_as_ull(da.x), Up[2 * j],     a0);
            a1 = ffma2(d_as_ull(da.y), Up[2 * j + 1], a1);
            a2 = ffma2(d_as_ull(db.x), Up[2 * j],     a2);
            a3 = ffma2(d_as_ull(db.y), Up[2 * j + 1], a3);
        }
        const float2 r0 = unpack2(a0), r1 = unpack2(a1);
        const float2 r2 = unpack2(a2), r3 = unpack2(a3);
        rec_sh[0 * G3 + g] = brg + ((r0.x + r0.y) + (r1.x + r1.y));
        rec_sh[1 * G3 + g] = brg + ((r2.x + r2.y) + (r3.x + r3.y));

        if (g < 256) {
            asm volatile("bar.sync 1, 384;" ::: "memory");
            const float* rs = rec_sh + gb * G3;
            const float* xs = xp_sh[cur] + gb * G3;
            const float rz = rs[gj], rr = rs[gj + 128], rh = rs[gj + 256];
            const float xz = xs[gj], xr = xs[gj + 128], xh = xs[gj + 256];
            const float z = fsigmoid(xz + rz);
            const float r = fsigmoid(xr + rr);
            const float hh = ftanh(fmaf(r, rh, xh));
            const float hold = h_sh[gb * H_ + gj];
            const float hn = z * hold + (1.f - z) * hh;
            h_sh[gb * H_ + gj] = hn;
            *out_ptr = hn;
            out_ptr += out_stride;
        } else {
            asm volatile("bar.arrive 1, 384;" ::: "memory");
        }
        __syncthreads();

        bufA[s & 1] = fa;
        bufB[s & 1] = fb;
        cur ^= 1;
    }

    if (g < 256) {
        out[(size_t)B_ * T_ * 2 * H_ + (size_t)dir * B_ * H_ +
            (size_t)(b0 + gb) * H_ + gj] = h_sh[gb * H_ + gj];
    }
}

// ---------------------------------------------------------------------------
// kernel_launch
// ---------------------------------------------------------------------------
extern "C" void kernel_launch(void* const* d_in, const int* in_sizes, int n_in,
                              void* d_out, int out_size) {
    const int*   enc   = (const int*)  d_in[0];
    const float* s_fwd = (const float*)d_in[1];
    const float* s_bck = (const float*)d_in[2];
    const float* emb   = (const float*)d_in[3];
    const float* W_f   = (const float*)d_in[4];
    const float* U_f   = (const float*)d_in[5];
    const float* b_f   = (const float*)d_in[6];
    const float* W_b   = (const float*)d_in[7];
    const float* U_b   = (const float*)d_in[8];
    const float* b_b   = (const float*)d_in[9];
    float* out = (float*)d_out;

    cudaFuncSetAttribute(proj_mma_kernel,
                         cudaFuncAttributeMaxDynamicSharedMemorySize, SMEMB);

    prep_kernel<<<EBLK + WBLK, 256>>>(emb, W_f, W_b);

    dim3 pgrid(VOCAB / 128, G3 / 128, 2);
    proj_mma_kernel<<<pgrid, 256, SMEMB>>>(b_f, b_b);

    dim3 sgrid(B_ / 2, 2);
    scan_kernel<<<sgrid, 384>>>(enc, s_fwd, s_bck, U_f, b_f, U_b, b_b, out);
}

// round 16
// speedup vs baseline: 1.1748x; 1.1748x over previous
#include <cuda_runtime.h>
#include <cuda_bf16.h>
#include <math.h>
#include <stdint.h>

#define VOCAB 32000
#define DIM   300
#define KPAD  304     // 19 * 16, zero-padded K
#define B_    128
#define T_    512
#define H_    128
#define G3    384     // 3*H

// Scratch (static device memory, allocation-free):
__device__ float g_proj[2][VOCAB * G3];                 // 98.3 MB
__device__ __nv_bfloat16 g_embH[VOCAB * KPAD];          // 19.5 MB
__device__ __nv_bfloat16 g_embL[VOCAB * KPAD];          // 19.5 MB
__device__ __nv_bfloat16 g_WH[2][G3 * KPAD];            // [dir][n][k] transposed
__device__ __nv_bfloat16 g_WL[2][G3 * KPAD];

// ---- packed f32x2 helpers ---------------------------------------------------
__device__ __forceinline__ unsigned long long ffma2(
    unsigned long long a, unsigned long long b, unsigned long long c) {
    unsigned long long d;
    asm("fma.rn.f32x2 %0, %1, %2, %3;" : "=l"(d) : "l"(a), "l"(b), "l"(c));
    return d;
}
__device__ __forceinline__ unsigned long long pack2(float lo, float hi) {
    unsigned long long r;
    asm("mov.b64 %0, {%1, %2};" : "=l"(r) : "f"(lo), "f"(hi));
    return r;
}
__device__ __forceinline__ float2 unpack2(unsigned long long v) {
    float lo, hi;
    asm("mov.b64 {%0, %1}, %2;" : "=f"(lo), "=f"(hi) : "l"(v));
    return make_float2(lo, hi);
}
__device__ __forceinline__ unsigned long long d_as_ull(double d) {
    return __double_as_longlong(d);
}
__device__ __forceinline__ float fsigmoid(float x) {
    const float e = __expf(-x);
    return __fdividef(1.f, 1.f + e);
}
__device__ __forceinline__ float ftanh(float y) {
    const float e = __expf(-2.f * y);
    const float s = __fdividef(1.f, 1.f + e);
    return fmaf(2.f, s, -1.f);
}

// ---- warp-MMA helpers (baseline PTX, sm_80+) -------------------------------
__device__ __forceinline__ uint32_t smem_u32(const void* p) {
    uint32_t a;
    asm("{ .reg .u64 t; cvta.to.shared.u64 t, %1; cvt.u32.u64 %0, t; }"
        : "=r"(a) : "l"(p));
    return a;
}
__device__ __forceinline__ void ldm_x4(uint32_t& r0, uint32_t& r1,
                                       uint32_t& r2, uint32_t& r3,
                                       uint32_t addr) {
    asm volatile("ldmatrix.sync.aligned.m8n8.x4.shared.b16 {%0,%1,%2,%3}, [%4];"
                 : "=r"(r0), "=r"(r1), "=r"(r2), "=r"(r3) : "r"(addr));
}
__device__ __forceinline__ void mma_bf16(float* c, const uint32_t* a,
                                         const uint32_t* b) {
    asm volatile(
        "mma.sync.aligned.m16n8k16.row.col.f32.bf16.bf16.f32 "
        "{%0,%1,%2,%3}, {%4,%5,%6,%7}, {%8,%9}, {%0,%1,%2,%3};"
        : "+f"(c[0]), "+f"(c[1]), "+f"(c[2]), "+f"(c[3])
        : "r"(a[0]), "r"(a[1]), "r"(a[2]), "r"(a[3]), "r"(b[0]), "r"(b[1]));
}
__device__ __forceinline__ void cp_async16(uint32_t smem_addr,
                                           const void* gptr) {
    asm volatile("cp.async.cg.shared.global [%0], [%1], 16;"
                 :: "r"(smem_addr), "l"(gptr));
}
#define CP_COMMIT() asm volatile("cp.async.commit_group;" ::: "memory")
#define CP_WAIT1()  asm volatile("cp.async.wait_group 1;" ::: "memory")

__device__ __forceinline__ void cvt8_hilo(const float* v, uint4& H, uint4& L) {
    uint32_t hw[4], lw[4];
    #pragma unroll
    for (int q = 0; q < 4; q++) {
        const __nv_bfloat16 h0 = __float2bfloat16(v[2 * q]);
        const __nv_bfloat16 h1 = __float2bfloat16(v[2 * q + 1]);
        const __nv_bfloat16 l0 = __float2bfloat16(v[2 * q] - __bfloat162float(h0));
        const __nv_bfloat16 l1 = __float2bfloat16(v[2 * q + 1] - __bfloat162float(h1));
        hw[q] = (uint32_t)__bfloat16_as_ushort(h0) |
                ((uint32_t)__bfloat16_as_ushort(h1) << 16);
        lw[q] = (uint32_t)__bfloat16_as_ushort(l0) |
                ((uint32_t)__bfloat16_as_ushort(l1) << 16);
    }
    H = make_uint4(hw[0], hw[1], hw[2], hw[3]);
    L = make_uint4(lw[0], lw[1], lw[2], lw[3]);
}

// ---------------------------------------------------------------------------
// Fused prep kernel: one-time fp32 -> bf16 hi/lo conversion.
// ---------------------------------------------------------------------------
#define EITEMS (VOCAB * (KPAD / 8))
#define WITEMS (2 * G3 * (KPAD / 8))
#define EBLK   ((EITEMS + 255) / 256)
#define WBLK   ((WITEMS + 255) / 256)

__global__ __launch_bounds__(256)
void prep_kernel(const float* __restrict__ emb,
                 const float* __restrict__ W_f,
                 const float* __restrict__ W_b) {
    if (blockIdx.x < EBLK) {
        const int idx = blockIdx.x * 256 + threadIdx.x;
        if (idx >= EITEMS) return;
        const int v = idx / (KPAD / 8);
        const int k0 = (idx % (KPAD / 8)) * 8;
        float val[8];
        const float* src = emb + (size_t)v * DIM + k0;
        if (k0 + 7 < DIM) {
            const float4 f0 = *reinterpret_cast<const float4*>(src);
            const float4 f1 = *reinterpret_cast<const float4*>(src + 4);
            val[0] = f0.x; val[1] = f0.y; val[2] = f0.z; val[3] = f0.w;
            val[4] = f1.x; val[5] = f1.y; val[6] = f1.z; val[7] = f1.w;
        } else {
            #pragma unroll
            for (int j = 0; j < 8; j++)
                val[j] = (k0 + j < DIM) ? src[j] : 0.f;
        }
        uint4 H, L;
        cvt8_hilo(val, H, L);
        *reinterpret_cast<uint4*>(&g_embH[(size_t)v * KPAD + k0]) = H;
        *reinterpret_cast<uint4*>(&g_embL[(size_t)v * KPAD + k0]) = L;
    } else {
        const int idx = (blockIdx.x - EBLK) * 256 + threadIdx.x;
        if (idx >= WITEMS) return;
        const int dir = idx / (G3 * (KPAD / 8));
        const int rem = idx % (G3 * (KPAD / 8));
        const int n   = rem / (KPAD / 8);
        const int k0  = (rem % (KPAD / 8)) * 8;
        const float* W = dir ? W_b : W_f;
        float val[8];
        #pragma unroll
        for (int j = 0; j < 8; j++) {
            const int k = k0 + j;
            val[j] = (k < DIM) ? W[(size_t)k * G3 + n] : 0.f;
        }
        uint4 H, L;
        cvt8_hilo(val, H, L);
        *reinterpret_cast<uint4*>(&g_WH[dir][(size_t)n * KPAD + k0]) = H;
        *reinterpret_cast<uint4*>(&g_WL[dir][(size_t)n * KPAD + k0]) = L;
    }
}

// ---------------------------------------------------------------------------
// Tensor-core projection (exact R11 best-measured config): 2-stage cp.async,
// 48-byte tile row pitch, CTA 128M x 128N, 8 warps, mma m16n8k16,
// 3-term bf16 split, fp32 accumulators. 48 KB static SMEM, 2 CTAs/SM.
// ---------------------------------------------------------------------------
#define NCH 19
#define ROWB 48
#define TILEB (128 * ROWB)              // 6144 B
#define STAGEB (4 * TILEB)              // 24576 B

__global__ __launch_bounds__(256, 2)
void proj_mma_kernel(const float* __restrict__ b_f,
                     const float* __restrict__ b_b) {
    __shared__ __align__(16) char smem[2 * STAGEB];   // 48 KB

    const int dir = blockIdx.z;
    const float* bi = dir ? b_b : b_f;   // row 0 = b_i
    const int vBase = blockIdx.x * 128;
    const int nBase = blockIdx.y * 128;

    const int tid  = threadIdx.x;
    const int lane = tid & 31;
    const int wid  = tid >> 5;
    const int wm   = (wid >> 2) * 64;
    const int wn   = (wid & 3) * 32;

    const int sr = tid >> 1;
    const int sk = (tid & 1) * 8;

    const __nv_bfloat16* embH = g_embH + (size_t)(vBase + sr) * KPAD + sk;
    const __nv_bfloat16* embL = g_embL + (size_t)(vBase + sr) * KPAD + sk;
    const __nv_bfloat16* WHp  = &g_WH[dir][(size_t)(nBase + sr) * KPAD + sk];
    const __nv_bfloat16* WLp  = &g_WL[dir][(size_t)(nBase + sr) * KPAD + sk];

    const uint32_t smem0 = smem_u32(smem);
    const uint32_t dst   = smem0 + (uint32_t)(sr * ROWB + sk * 2);

    auto issue_stage = [&](int ch, int buf) {
        const int kc = ch * 16;
        const uint32_t o = (uint32_t)(buf * STAGEB);
        cp_async16(dst + o + 0 * TILEB, embH + kc);
        cp_async16(dst + o + 1 * TILEB, embL + kc);
        cp_async16(dst + o + 2 * TILEB, WHp + kc);
        cp_async16(dst + o + 3 * TILEB, WLp + kc);
    };

    const int grp = lane >> 3;
    const int rin = lane & 7;
    const int a_row_off = (grp & 1) * 8 + rin;
    const int a_col_off = (grp >> 1) * 8;
    const int b_row_off = (grp >> 1) * 8 + rin;
    const int b_col_off = (grp & 1) * 8;

    float acc[4][4][4];
    #pragma unroll
    for (int i = 0; i < 4; i++)
        #pragma unroll
        for (int j = 0; j < 4; j++)
            #pragma unroll
            for (int q = 0; q < 4; q++) acc[i][j][q] = 0.f;

    issue_stage(0, 0); CP_COMMIT();
    issue_stage(1, 1); CP_COMMIT();

    for (int ch = 0; ch < NCH; ch++) {
        const int buf = ch & 1;
        CP_WAIT1();
        __syncthreads();

        const uint32_t base = smem0 + (uint32_t)(buf * STAGEB);
        const uint32_t ah = base + 0 * TILEB;
        const uint32_t al = base + 1 * TILEB;
        const uint32_t bh = base + 2 * TILEB;
        const uint32_t bl = base + 3 * TILEB;

        uint32_t Bhf[2][4], Blf[2][4];
        #pragma unroll
        for (int ip = 0; ip < 2; ip++) {
            const uint32_t boff =
                (uint32_t)((wn + ip * 16 + b_row_off) * ROWB + b_col_off * 2);
            ldm_x4(Bhf[ip][0], Bhf[ip][1], Bhf[ip][2], Bhf[ip][3], bh + boff);
            ldm_x4(Blf[ip][0], Blf[ip][1], Blf[ip][2], Blf[ip][3], bl + boff);
        }
        uint32_t Af[4][4];
        #pragma unroll
        for (int im = 0; im < 4; im++) {
            const uint32_t aoff =
                (uint32_t)((wm + im * 16 + a_row_off) * ROWB + a_col_off * 2);
            ldm_x4(Af[im][0], Af[im][1], Af[im][2], Af[im][3], ah + aoff);
        }
        #pragma unroll
        for (int im = 0; im < 4; im++)
            #pragma unroll
            for (int ip = 0; ip < 2; ip++) {
                mma_bf16(acc[im][ip * 2 + 0], Af[im], &Bhf[ip][0]);
                mma_bf16(acc[im][ip * 2 + 1], Af[im], &Bhf[ip][2]);
                mma_bf16(acc[im][ip * 2 + 0], Af[im], &Blf[ip][0]);
                mma_bf16(acc[im][ip * 2 + 1], Af[im], &Blf[ip][2]);
            }
        #pragma unroll
        for (int im = 0; im < 4; im++) {
            const uint32_t aoff =
                (uint32_t)((wm + im * 16 + a_row_off) * ROWB + a_col_off * 2);
            ldm_x4(Af[im][0], Af[im][1], Af[im][2], Af[im][3], al + aoff);
        }
        #pragma unroll
        for (int im = 0; im < 4; im++)
            #pragma unroll
            for (int ip = 0; ip < 2; ip++) {
                mma_bf16(acc[im][ip * 2 + 0], Af[im], &Bhf[ip][0]);
                mma_bf16(acc[im][ip * 2 + 1], Af[im], &Bhf[ip][2]);
            }
        __syncthreads();

        if (ch + 2 < NCH) issue_stage(ch + 2, buf);
        CP_COMMIT();
    }

    float* outp = g_proj[dir];
    #pragma unroll
    for (int im = 0; im < 4; im++) {
        const int m = vBase + wm + im * 16 + (lane >> 2);
        #pragma unroll
        for (int in = 0; in < 4; in++) {
            const int n = nBase + wn + in * 8 + (lane & 3) * 2;
            const float b0 = __ldg(&bi[n]);
            const float b1 = __ldg(&bi[n + 1]);
            float* o0 = outp + (size_t)m * G3 + n;
            float* o1 = o0 + 8 * G3;
            *reinterpret_cast<float2*>(o0) =
                make_float2(acc[im][in][0] + b0, acc[im][in][1] + b1);
            *reinterpret_cast<float2*>(o1) =
                make_float2(acc[im][in][2] + b0, acc[im][in][3] + b1);
        }
    }
}

// ---------------------------------------------------------------------------
// GRU scan kernel, K-SPLIT AT CONSTANT THREAD COUNT (384 threads).
// Thread t handles TWO columns (c, c+192) over HALF of K (kh = t/192):
// per-thread h traffic halves (512B/step), FFMA2 count unchanged (128),
// barrier topology identical to the frozen 543us scan.
// Partials: recA (kh=0, + b_r) and recB (kh=1); gates sum the pair.
// ---------------------------------------------------------------------------
__global__ __launch_bounds__(384, 1)
void scan_kernel(const int*   __restrict__ enc,
                 const float* __restrict__ state_fwd,
                 const float* __restrict__ state_back,
                 const float* __restrict__ U_f,
                 const float* __restrict__ b_f,
                 const float* __restrict__ U_b,
                 const float* __restrict__ b_b,
                 float*       __restrict__ out) {
    const int dir = blockIdx.y;
    const int b0  = blockIdx.x * 2;
    const int g   = threadIdx.x;          // 0..383
    const int kh  = (g >= 192);           // K half
    const int c   = kh ? g - 192 : g;     // column base 0..191 (also c+192)

    const float* U     = dir ? U_b : U_f;
    const float* br    = (dir ? b_b : b_f) + G3;   // row 1 = b_r
    const float* state = dir ? state_back : state_fwd;
    const float* proj  = g_proj[dir];

    __shared__ __align__(16) float h_sh[2 * H_];
    __shared__ float recA_sh[2 * G3];
    __shared__ float recB_sh[2 * G3];
    __shared__ float xp_sh[2][2 * G3];
    __shared__ int   tok_sh[2][T_];

    // U for this thread's K-half, two columns, packed K-pairs
    unsigned long long Up0[32], Up1[32];
    #pragma unroll
    for (int i = 0; i < 32; i++) {
        const int k = kh * 64 + 2 * i;
        Up0[i] = pack2(U[(size_t)k * G3 + c],       U[(size_t)(k + 1) * G3 + c]);
        Up1[i] = pack2(U[(size_t)k * G3 + c + 192], U[(size_t)(k + 1) * G3 + c + 192]);
    }
    const float brg0 = kh ? 0.f : br[c];
    const float brg1 = kh ? 0.f : br[c + 192];

    for (int i = g; i < 2 * T_; i += 384) {
        const int b = i >> 9, t = i & (T_ - 1);
        tok_sh[b][t] = enc[(size_t)(b0 + b) * T_ + t];
    }

    const int gb = g >> 7, gj = g & 127;          // valid for g < 256
    float* out_ptr = out + (size_t)((b0 + gb) * T_ + (dir ? T_ - 1 : 0)) * (2 * H_)
                   + dir * H_ + gj;
    const long out_stride = (dir ? -1 : 1) * (long)(2 * H_);

    if (g < 256)
        h_sh[gb * H_ + gj] = state[(size_t)(b0 + gb) * H_ + gj];

    // xp pipeline: thread g owns column g for both batches (unchanged)
    float bufA[2], bufB[2];
    {
        const int t0 = dir ? (T_ - 1) : 0;
        const int t1 = dir ? (T_ - 2) : 1;
        xp_sh[0][0 * G3 + g] = proj[(size_t)enc[(size_t)b0 * T_ + t0] * G3 + g];
        xp_sh[0][1 * G3 + g] = proj[(size_t)enc[(size_t)(b0 + 1) * T_ + t0] * G3 + g];
        bufA[1] = __ldg(&proj[(size_t)enc[(size_t)b0 * T_ + t1] * G3 + g]);
        bufB[1] = __ldg(&proj[(size_t)enc[(size_t)(b0 + 1) * T_ + t1] * G3 + g]);
        bufA[0] = 0.f; bufB[0] = 0.f;
    }
    __syncthreads();

    float* recP = kh ? recB_sh : recA_sh;
    const double2* hp0 = reinterpret_cast<const double2*>(h_sh) + kh * 16;
    const double2* hp1 = hp0 + 32;   // batch 1 (h_sh + 128 floats = +32 double2)

    int cur = 0;
    #pragma unroll 2
    for (int s = 0; s < T_; s++) {
        const int s2 = (s + 2 < T_) ? (s + 2) : (T_ - 1);
        const int t2 = dir ? (T_ - 1 - s2) : s2;
        const float fa = __ldg(&proj[(size_t)tok_sh[0][t2] * G3 + g]);
        const float fb = __ldg(&proj[(size_t)tok_sh[1][t2] * G3 + g]);

        xp_sh[cur ^ 1][0 * G3 + g] = bufA[(s + 1) & 1];
        xp_sh[cur ^ 1][1 * G3 + g] = bufB[(s + 1) & 1];

        // half-K partial dot for 2 columns x 2 batches (128 FFMA2 total)
        unsigned long long a00 = 0ull, a01 = 0ull;  // batch0: col c, col c+192
        unsigned long long a10 = 0ull, a11 = 0ull;  // batch1
        #pragma unroll
        for (int j = 0; j < 16; j++) {
            const double2 da = hp0[j];
            const double2 db = hp1[j];
            a00 = ffma2(d_as_ull(da.x), Up0[2 * j],     a00);
            a00 = ffma2(d_as_ull(da.y), Up0[2 * j + 1], a00);
            a01 = ffma2(d_as_ull(da.x), Up1[2 * j],     a01);
            a01 = ffma2(d_as_ull(da.y), Up1[2 * j + 1], a01);
            a10 = ffma2(d_as_ull(db.x), Up0[2 * j],     a10);
            a10 = ffma2(d_as_ull(db.y), Up0[2 * j + 1], a10);
            a11 = ffma2(d_as_ull(db.x), Up1[2 * j],     a11);
            a11 = ffma2(d_as_ull(db.y), Up1[2 * j + 1], a11);
        }
        const float2 r00 = unpack2(a00), r01 = unpack2(a01);
        const float2 r10 = unpack2(a10), r11 = unpack2(a11);
        recP[0 * G3 + c]       = brg0 + r00.x + r00.y;
        recP[0 * G3 + c + 192] = brg1 + r01.x + r01.y;
        recP[1 * G3 + c]       = brg0 + r10.x + r10.y;
        recP[1 * G3 + c + 192] = brg1 + r11.x + r11.y;

        if (g < 256) {
            asm volatile("bar.sync 1, 384;" ::: "memory");
            const float* rA = recA_sh + gb * G3;
            const float* rB = recB_sh + gb * G3;
            const float* xs = xp_sh[cur] + gb * G3;
            const float rz = rA[gj]       + rB[gj];
            const float rr = rA[gj + 128] + rB[gj + 128];
            const float rh = rA[gj + 256] + rB[gj + 256];
            const float xz = xs[gj], xr = xs[gj + 128], xh = xs[gj + 256];
            const float z = fsigmoid(xz + rz);
            const float r = fsigmoid(xr + rr);
            const float hh = ftanh(fmaf(r, rh, xh));
            const float hold = h_sh[gb * H_ + gj];
            const float hn = fmaf(z, hold - hh, hh);
            h_sh[gb * H_ + gj] = hn;
            *out_ptr = hn;
            out_ptr += out_stride;
        } else {
            asm volatile("bar.arrive 1, 384;" ::: "memory");
        }
        __syncthreads();

        bufA[s & 1] = fa;
        bufB[s & 1] = fb;
        cur ^= 1;
    }

    if (g < 256) {
        out[(size_t)B_ * T_ * 2 * H_ + (size_t)dir * B_ * H_ +
            (size_t)(b0 + gb) * H_ + gj] = h_sh[gb * H_ + gj];
    }
}

// ---------------------------------------------------------------------------
// kernel_launch
// ---------------------------------------------------------------------------
extern "C" void kernel_launch(void* const* d_in, const int* in_sizes, int n_in,
                              void* d_out, int out_size) {
    const int*   enc   = (const int*)  d_in[0];
    const float* s_fwd = (const float*)d_in[1];
    const float* s_bck = (const float*)d_in[2];
    const float* emb   = (const float*)d_in[3];
    const float* W_f   = (const float*)d_in[4];
    const float* U_f   = (const float*)d_in[5];
    const float* b_f   = (const float*)d_in[6];
    const float* W_b   = (const float*)d_in[7];
    const float* U_b   = (const float*)d_in[8];
    const float* b_b   = (const float*)d_in[9];
    float* out = (float*)d_out;

    prep_kernel<<<EBLK + WBLK, 256>>>(emb, W_f, W_b);

    dim3 pgrid(VOCAB / 128, G3 / 128, 2);
    proj_mma_kernel<<<pgrid, 256>>>(b_f, b_b);

    dim3 sgrid(B_ / 2, 2);
    scan_kernel<<<sgrid, 384>>>(enc, s_fwd, s_bck, U_f, b_f, U_b, b_b, out);
}